// round 6
// baseline (speedup 1.0000x reference)
#include <cuda_runtime.h>
#include <cuda_bf16.h>
#include <cstdint>
#include <cstddef>

#define NN     50000
#define NE     800000
#define INC    128
#define HID    64
#define HEADS  4
#define D1     256          // HEADS*HID
#define OUTC   10
#define NG     500
#define NEG    0.2f

// ---------------- scratch (device globals; allocation-free) ----------------
__device__ __align__(16) float g_h1  [NN * D1];      // x @ W1
__device__ __align__(16) float g_out1[NN * D1];      // GAT1 aggregate -> relu(out+b1)
__device__ __align__(16) float g_als1[NN * HEADS];
__device__ __align__(16) float g_ald1[NN * HEADS];
__device__ __align__(16) float g_self1[NN * HEADS];
__device__ __align__(16) float g_m1  [NN * HEADS];
__device__ __align__(16) float g_den1[NN * HEADS];
__device__             unsigned g_m1o[NN * HEADS];
__device__ __align__(16) float g_ev1 [(size_t)NE * HEADS];
__device__ __align__(16) float g_h2  [NN * HID];     // relu1 @ W2
__device__ __align__(16) float g_out2[NN * HID];
__device__ float g_als2[NN], g_ald2[NN], g_self2[NN], g_m2[NN], g_den2[NN];
__device__ unsigned g_m2o[NN];
__device__ float g_ev2[NE];
__device__ __align__(16) float g_pool[NG * HID];

// converted (int32) indices — robust to harness delivering int32 OR int64
__device__ int g_is64;
__device__ int g_src[NE];
__device__ int g_dst[NE];
__device__ int g_bat[NN];

// ---------------- helpers ----------------
__device__ __forceinline__ float leaky(float v) { return v > 0.f ? v : NEG * v; }

// monotone float<->uint map for atomicMax on floats
__device__ __forceinline__ unsigned ford(float f) {
    unsigned u = __float_as_uint(f);
    return (u & 0x80000000u) ? ~u : (u | 0x80000000u);
}
__device__ __forceinline__ float fdec(unsigned u) {
    return __uint_as_float((u & 0x80000000u) ? (u & 0x7FFFFFFFu) : ~u);
}

// vectorized global reduction (sm_90+): 4x fewer RED instructions vs scalar atomicAdd
__device__ __forceinline__ void red4(float* p, float4 v) {
    asm volatile("red.global.add.v4.f32 [%0], {%1,%2,%3,%4};"
                 :: "l"(p), "f"(v.x), "f"(v.y), "f"(v.z), "f"(v.w) : "memory");
}

// ---------------- index dtype detection + conversion ----------------
// If edge_index is int64, values < 2^31 => every odd int32 word is 0.
// If int32, odd words are random node ids in [0, 50000) — all-zero is impossible
// in practice over 64 samples.
__global__ void detect_k(const int* __restrict__ raw) {
    if (blockIdx.x == 0 && threadIdx.x == 0) {
        int acc = 0;
#pragma unroll 1
        for (int i = 1; i < 128; i += 2) acc |= raw[i];
        g_is64 = (acc == 0) ? 1 : 0;
    }
}

__global__ void cvt_edges_k(const int* __restrict__ raw) {
    int e = blockIdx.x * blockDim.x + threadIdx.x;
    if (e >= NE) return;
    if (g_is64) {
        const long long* p = (const long long*)raw;
        g_src[e] = (int)p[e];
        g_dst[e] = (int)p[(size_t)NE + e];
    } else {
        g_src[e] = raw[e];
        g_dst[e] = raw[NE + e];
    }
}

__global__ void cvt_batch_k(const int* __restrict__ raw) {
    int n = blockIdx.x * blockDim.x + threadIdx.x;
    if (n >= NN) return;
    if (g_is64) {
        const long long* p = (const long long*)raw;
        g_bat[n] = (int)p[n];
    } else {
        g_bat[n] = raw[n];
    }
}

// ---------------- SGEMM: C[M,N] = A[M,K] @ B[K,N] ----------------
// BM=128, BN=64, BK=16; 256 threads; 8x4 per-thread tile. K%16==0, N%64==0 assumed.
__global__ __launch_bounds__(256) void sgemm_k(const float* __restrict__ A,
                                               const float* __restrict__ B,
                                               float* __restrict__ C,
                                               int M, int N, int K) {
    __shared__ __align__(16) float As[16][128];
    __shared__ __align__(16) float Bs[16][64];
    const int tid = threadIdx.x;
    const int tx = tid & 15, ty = tid >> 4;
    const int m0 = blockIdx.y * 128, n0 = blockIdx.x * 64;

    float acc[8][4];
#pragma unroll
    for (int i = 0; i < 8; i++)
#pragma unroll
        for (int j = 0; j < 4; j++) acc[i][j] = 0.f;

    for (int k0 = 0; k0 < K; k0 += 16) {
#pragma unroll
        for (int v = 0; v < 2; v++) {              // A tile: 128x16, 2 float4 per thread
            int id  = tid + v * 256;
            int row = id >> 2;
            int kc  = (id & 3) << 2;
            float4 f = make_float4(0.f, 0.f, 0.f, 0.f);
            int gr = m0 + row;
            if (gr < M) f = *(const float4*)(A + (size_t)gr * K + k0 + kc);
            As[kc + 0][row] = f.x; As[kc + 1][row] = f.y;
            As[kc + 2][row] = f.z; As[kc + 3][row] = f.w;
        }
        {                                          // B tile: 16x64, 1 float4 per thread
            int kk = tid >> 4;
            int nc = (tid & 15) << 2;
            *(float4*)&Bs[kk][nc] = *(const float4*)(B + (size_t)(k0 + kk) * N + n0 + nc);
        }
        __syncthreads();
#pragma unroll
        for (int kk = 0; kk < 16; kk++) {
            float a[8], b[4];
            *(float4*)&a[0] = *(const float4*)&As[kk][ty * 8];
            *(float4*)&a[4] = *(const float4*)&As[kk][ty * 8 + 4];
            *(float4*)&b[0] = *(const float4*)&Bs[kk][tx * 4];
#pragma unroll
            for (int i = 0; i < 8; i++)
#pragma unroll
                for (int j = 0; j < 4; j++) acc[i][j] = fmaf(a[i], b[j], acc[i][j]);
        }
        __syncthreads();
    }
#pragma unroll
    for (int i = 0; i < 8; i++) {
        int gr = m0 + ty * 8 + i;
        if (gr < M)
            *(float4*)(C + (size_t)gr * N + n0 + tx * 4) =
                make_float4(acc[i][0], acc[i][1], acc[i][2], acc[i][3]);
    }
}

// ---------------- layer 1: attention coefficients ----------------
__global__ void al1_k(const float* __restrict__ a_src, const float* __restrict__ a_dst) {
    int t = blockIdx.x * blockDim.x + threadIdx.x;
    if (t >= NN * HEADS) return;
    int n = t >> 2, h = t & 3;
    const float4* hr = (const float4*)(g_h1 + (size_t)n * D1 + h * HID);
    const float4* as = (const float4*)(a_src + h * HID);
    const float4* ad = (const float4*)(a_dst + h * HID);
    float ss = 0.f, sd = 0.f;
#pragma unroll
    for (int j = 0; j < 16; j++) {
        float4 v = hr[j], a = as[j], b = ad[j];
        ss += v.x * a.x + v.y * a.y + v.z * a.z + v.w * a.w;
        sd += v.x * b.x + v.y * b.y + v.z * b.z + v.w * b.w;
    }
    g_als1[t] = ss;
    g_ald1[t] = sd;
}

__global__ void self1_k() {
    int t = blockIdx.x * blockDim.x + threadIdx.x;
    if (t >= NN * HEADS) return;
    float s = leaky(g_als1[t] + g_ald1[t]);   // self-loop logit
    g_self1[t] = s;
    g_m1o[t] = ford(s);                        // init running max with self
}

__global__ void edgeA1_k() {
    int e = blockIdx.x * blockDim.x + threadIdx.x;
    if (e >= NE) return;
    int s = g_src[e], d = g_dst[e];
    float4 as = *(const float4*)(g_als1 + s * 4);
    float4 ad = *(const float4*)(g_ald1 + d * 4);
    float4 v = make_float4(leaky(as.x + ad.x), leaky(as.y + ad.y),
                           leaky(as.z + ad.z), leaky(as.w + ad.w));
    *(float4*)(g_ev1 + (size_t)e * 4) = v;
    atomicMax(&g_m1o[d * 4 + 0], ford(v.x));
    atomicMax(&g_m1o[d * 4 + 1], ford(v.y));
    atomicMax(&g_m1o[d * 4 + 2], ford(v.z));
    atomicMax(&g_m1o[d * 4 + 3], ford(v.w));
}

__global__ void mden1_k() {
    int t = blockIdx.x * blockDim.x + threadIdx.x;
    if (t >= NN * HEADS) return;
    float m = fdec(g_m1o[t]);
    g_m1[t] = m;
    g_den1[t] = expf(g_self1[t] - m) + 1e-16f;   // self contribution + ref epsilon
}

__global__ void edgeB1_k() {
    int e = blockIdx.x * blockDim.x + threadIdx.x;
    if (e >= NE) return;
    int d = g_dst[e];
    float4 ev = *(const float4*)(g_ev1 + (size_t)e * 4);
    float4 m  = *(const float4*)(g_m1 + d * 4);
    atomicAdd(&g_den1[d * 4 + 0], expf(ev.x - m.x));
    atomicAdd(&g_den1[d * 4 + 1], expf(ev.y - m.y));
    atomicAdd(&g_den1[d * 4 + 2], expf(ev.z - m.z));
    atomicAdd(&g_den1[d * 4 + 3], expf(ev.w - m.w));
}

__global__ void selfmsg1_k() {
    int t = blockIdx.x * blockDim.x + threadIdx.x;   // (node, float4-chunk)
    if (t >= NN * 64) return;
    int n = t >> 6, q = t & 63, h = q >> 4;
    float w = expf(g_self1[n * 4 + h] - g_m1[n * 4 + h]) / g_den1[n * 4 + h];
    float4 v = ((const float4*)g_h1)[t];
    ((float4*)g_out1)[t] = make_float4(v.x * w, v.y * w, v.z * w, v.w * w);
}

// heavy pass: one warp per edge, 256 channels (8 floats / lane), vectorized RED
__global__ __launch_bounds__(256) void edgeC1_k() {
    int warp = (blockIdx.x * blockDim.x + threadIdx.x) >> 5;
    int lane = threadIdx.x & 31;
    if (warp >= NE) return;
    int s = g_src[warp], d = g_dst[warp];
    int h = lane >> 3;
    float alpha = expf(g_ev1[(size_t)warp * 4 + h] - g_m1[d * 4 + h]) / g_den1[d * 4 + h];
    const float4* hs = (const float4*)(g_h1 + (size_t)s * D1) + lane * 2;
    float4 v0 = hs[0], v1 = hs[1];
    float* po = g_out1 + (size_t)d * D1 + lane * 8;
    red4(po,     make_float4(v0.x * alpha, v0.y * alpha, v0.z * alpha, v0.w * alpha));
    red4(po + 4, make_float4(v1.x * alpha, v1.y * alpha, v1.z * alpha, v1.w * alpha));
}

__global__ void finrelu1_k(const float* __restrict__ b1) {
    int t = blockIdx.x * blockDim.x + threadIdx.x;
    if (t >= NN * 64) return;
    int q = t & 63;
    float4 v = ((const float4*)g_out1)[t];
    float4 b = ((const float4*)b1)[q];
    ((float4*)g_out1)[t] = make_float4(fmaxf(v.x + b.x, 0.f), fmaxf(v.y + b.y, 0.f),
                                       fmaxf(v.z + b.z, 0.f), fmaxf(v.w + b.w, 0.f));
}

// ---------------- layer 2 (H=1, C=64) ----------------
__global__ void al2_k(const float* __restrict__ a_src, const float* __restrict__ a_dst) {
    int n = blockIdx.x * blockDim.x + threadIdx.x;
    if (n >= NN) return;
    const float4* hr = (const float4*)(g_h2 + (size_t)n * HID);
    const float4* as = (const float4*)a_src;
    const float4* ad = (const float4*)a_dst;
    float ss = 0.f, sd = 0.f;
#pragma unroll
    for (int j = 0; j < 16; j++) {
        float4 v = hr[j], a = as[j], b = ad[j];
        ss += v.x * a.x + v.y * a.y + v.z * a.z + v.w * a.w;
        sd += v.x * b.x + v.y * b.y + v.z * b.z + v.w * b.w;
    }
    g_als2[n] = ss;
    g_ald2[n] = sd;
}

__global__ void self2_k() {
    int n = blockIdx.x * blockDim.x + threadIdx.x;
    if (n >= NN) return;
    float s = leaky(g_als2[n] + g_ald2[n]);
    g_self2[n] = s;
    g_m2o[n] = ford(s);
}

__global__ void edgeA2_k() {
    int e = blockIdx.x * blockDim.x + threadIdx.x;
    if (e >= NE) return;
    int s = g_src[e], d = g_dst[e];
    float v = leaky(g_als2[s] + g_ald2[d]);
    g_ev2[e] = v;
    atomicMax(&g_m2o[d], ford(v));
}

__global__ void mden2_k() {
    int n = blockIdx.x * blockDim.x + threadIdx.x;
    if (n >= NN) return;
    float m = fdec(g_m2o[n]);
    g_m2[n] = m;
    g_den2[n] = expf(g_self2[n] - m) + 1e-16f;
}

__global__ void edgeB2_k() {
    int e = blockIdx.x * blockDim.x + threadIdx.x;
    if (e >= NE) return;
    int d = g_dst[e];
    atomicAdd(&g_den2[d], expf(g_ev2[e] - g_m2[d]));
}

__global__ void selfmsg2_k() {
    int t = blockIdx.x * blockDim.x + threadIdx.x;   // (node, float4-chunk) 16/node
    if (t >= NN * 16) return;
    int n = t >> 4;
    float w = expf(g_self2[n] - g_m2[n]) / g_den2[n];
    float4 v = ((const float4*)g_h2)[t];
    ((float4*)g_out2)[t] = make_float4(v.x * w, v.y * w, v.z * w, v.w * w);
}

__global__ void edgeC2_k() {
    int t = blockIdx.x * blockDim.x + threadIdx.x;   // (edge, float4-chunk) 16/edge
    if (t >= NE * 16) return;
    int e = t >> 4, q = t & 15;
    int s = g_src[e], d = g_dst[e];
    float alpha = expf(g_ev2[e] - g_m2[d]) / g_den2[d];
    float4 v = ((const float4*)g_h2)[(size_t)s * 16 + q];
    red4(g_out2 + (size_t)d * HID + q * 4,
         make_float4(v.x * alpha, v.y * alpha, v.z * alpha, v.w * alpha));
}

// ---------------- pooling + classifier ----------------
__global__ void zeropool_k() {
    int t = blockIdx.x * blockDim.x + threadIdx.x;
    if (t < NG * HID) g_pool[t] = 0.f;
}

__global__ void pool_k(const float* __restrict__ b2) {
    int t = blockIdx.x * blockDim.x + threadIdx.x;   // (node, float4-chunk)
    if (t >= NN * 16) return;
    int n = t >> 4, q = t & 15;
    int g = g_bat[n];
    float4 v = ((const float4*)g_out2)[t];
    float4 b = ((const float4*)b2)[q];
    red4(&g_pool[g * HID + q * 4],
         make_float4(v.x + b.x, v.y + b.y, v.z + b.z, v.w + b.w));
}

__global__ void cls_k(const float* __restrict__ fcw, const float* __restrict__ fcb,
                      float* __restrict__ out) {
    int g = blockIdx.x * blockDim.x + threadIdx.x;
    if (g >= NG) return;
    float l[OUTC];
#pragma unroll
    for (int j = 0; j < OUTC; j++) l[j] = fcb[j];
    for (int k = 0; k < HID; k++) {
        float p = g_pool[g * HID + k];
#pragma unroll
        for (int j = 0; j < OUTC; j++) l[j] = fmaf(p, fcw[k * OUTC + j], l[j]);
    }
    float mx = l[0];
#pragma unroll
    for (int j = 1; j < OUTC; j++) mx = fmaxf(mx, l[j]);
    float s = 0.f;
#pragma unroll
    for (int j = 0; j < OUTC; j++) s += expf(l[j] - mx);
    float lse = mx + logf(s);
#pragma unroll
    for (int j = 0; j < OUTC; j++) out[g * OUTC + j] = l[j] - lse;
}

// ---------------- launch ----------------
extern "C" void kernel_launch(void* const* d_in, const int* in_sizes, int n_in,
                              void* d_out, int out_size) {
    const float* x      = (const float*)d_in[0];
    const int*   ei_raw = (const int*)d_in[1];    // int32 OR int64 — detected on device
    const int*   b_raw  = (const int*)d_in[2];
    const float* W1     = (const float*)d_in[3];
    const float* a_src1 = (const float*)d_in[4];
    const float* a_dst1 = (const float*)d_in[5];
    const float* b1     = (const float*)d_in[6];
    const float* W2     = (const float*)d_in[7];
    const float* a_src2 = (const float*)d_in[8];
    const float* a_dst2 = (const float*)d_in[9];
    const float* b2     = (const float*)d_in[10];
    const float* fcw    = (const float*)d_in[11];
    const float* fcb    = (const float*)d_in[12];
    float*       out    = (float*)d_out;

    void *p_h1, *p_out1, *p_h2;
    cudaGetSymbolAddress(&p_h1, g_h1);
    cudaGetSymbolAddress(&p_out1, g_out1);
    cudaGetSymbolAddress(&p_h2, g_h2);

    const int T = 256;
    const int gN4  = (NN * HEADS + T - 1) / T;
    const int gN   = (NN + T - 1) / T;
    const int gE   = (NE + T - 1) / T;
    const int gN64 = (NN * 64 + T - 1) / T;
    const int gN16 = (NN * 16 + T - 1) / T;
    const int gE16 = (NE * 16 + T - 1) / T;
    const int gEw  = (NE * 32 + T - 1) / T;

    // ---- index conversion (dtype-robust) ----
    detect_k<<<1, 32>>>(ei_raw);
    cvt_edges_k<<<gE, T>>>(ei_raw);
    cvt_batch_k<<<gN, T>>>(b_raw);

    // ---- GAT layer 1 ----
    sgemm_k<<<dim3(D1 / 64, (NN + 127) / 128), 256>>>(x, W1, (float*)p_h1, NN, D1, INC);
    al1_k<<<gN4, T>>>(a_src1, a_dst1);
    self1_k<<<gN4, T>>>();
    edgeA1_k<<<gE, T>>>();
    mden1_k<<<gN4, T>>>();
    edgeB1_k<<<gE, T>>>();
    selfmsg1_k<<<gN64, T>>>();
    edgeC1_k<<<gEw, T>>>();
    finrelu1_k<<<gN64, T>>>(b1);

    // ---- GAT layer 2 ----
    sgemm_k<<<dim3(HID / 64, (NN + 127) / 128), 256>>>((const float*)p_out1, W2,
                                                       (float*)p_h2, NN, HID, D1);
    al2_k<<<gN, T>>>(a_src2, a_dst2);
    self2_k<<<gN, T>>>();
    edgeA2_k<<<gE, T>>>();
    mden2_k<<<gN, T>>>();
    edgeB2_k<<<gE, T>>>();
    selfmsg2_k<<<gN16, T>>>();
    edgeC2_k<<<gE16, T>>>();

    // ---- pool + classify ----
    zeropool_k<<<(NG * HID + T - 1) / T, T>>>();
    pool_k<<<gN16, T>>>(b2);
    cls_k<<<(NG + T - 1) / T, T>>>(fcw, fcb, out);
}

// round 8
// speedup vs baseline: 1.6308x; 1.6308x over previous
#include <cuda_runtime.h>
#include <cuda_bf16.h>
#include <cstdint>
#include <cstddef>

#define NN     50000
#define NE     800000
#define INC    128
#define HID    64
#define HEADS  4
#define D1     256          // HEADS*HID
#define OUTC   10
#define NG     500
#define NEG    0.2f

// ---------------- scratch (device globals; allocation-free) ----------------
__device__ __align__(16) float g_h1  [NN * D1];      // x @ W1
__device__ __align__(16) float g_out1[NN * D1];      // relu(GAT1 + b1)
__device__ __align__(16) float g_als1[NN * HEADS];
__device__ __align__(16) float g_ald1[NN * HEADS];
__device__ __align__(16) float g_h2  [NN * HID];     // out1 @ W2
__device__ float g_als2[NN], g_ald2[NN];
__device__ __align__(16) float g_pool[NG * HID];

// index handling + CSR (dst-sorted)
__device__ int g_is64;
__device__ int g_src[NE];
__device__ int g_dst[NE];
__device__ int g_bat[NN];
__device__ int g_deg[NN];
__device__ int g_row[NN + 1];
__device__ int g_cur[NN];
__device__ int g_csr_src[NE];

// ---------------- helpers ----------------
__device__ __forceinline__ float leaky(float v) { return v > 0.f ? v : NEG * v; }

__device__ __forceinline__ void red4(float* p, float4 v) {
    asm volatile("red.global.add.v4.f32 [%0], {%1,%2,%3,%4};"
                 :: "l"(p), "f"(v.x), "f"(v.y), "f"(v.z), "f"(v.w) : "memory");
}

// ---------------- index dtype detection + conversion + degree histogram ----
__global__ void detect_k(const int* __restrict__ raw) {
    if (blockIdx.x == 0 && threadIdx.x == 0) {
        int acc = 0;
#pragma unroll 1
        for (int i = 1; i < 128; i += 2) acc |= raw[i];
        g_is64 = (acc == 0) ? 1 : 0;   // int64 little-endian: high words all zero
    }
}

__global__ void zero_deg_k() {
    int n = blockIdx.x * blockDim.x + threadIdx.x;
    if (n < NN) g_deg[n] = 0;
}

__global__ void cvt_edges_k(const int* __restrict__ raw) {
    int e = blockIdx.x * blockDim.x + threadIdx.x;
    if (e >= NE) return;
    int s, d;
    if (g_is64) {
        const long long* p = (const long long*)raw;
        s = (int)p[e];
        d = (int)p[(size_t)NE + e];
    } else {
        s = raw[e];
        d = raw[NE + e];
    }
    g_src[e] = s;
    g_dst[e] = d;
    atomicAdd(&g_deg[d], 1);
}

__global__ void cvt_batch_k(const int* __restrict__ raw) {
    int n = blockIdx.x * blockDim.x + threadIdx.x;
    if (n >= NN) return;
    if (g_is64) {
        const long long* p = (const long long*)raw;
        g_bat[n] = (int)p[n];
    } else {
        g_bat[n] = raw[n];
    }
}

// single-block exclusive scan over g_deg -> g_row (NN+1 entries); also inits g_cur
__global__ __launch_bounds__(1024) void scan_k() {
    __shared__ int wsum[32];
    __shared__ int s_carry;
    const int tid = threadIdx.x, lane = tid & 31, wid = tid >> 5;
    if (tid == 0) s_carry = 0;
    __syncthreads();
    for (int base = 0; base < NN; base += 1024) {
        int i = base + tid;
        int v = (i < NN) ? g_deg[i] : 0;
        // warp inclusive scan
        int incl = v;
#pragma unroll
        for (int off = 1; off < 32; off <<= 1) {
            int t = __shfl_up_sync(0xFFFFFFFFu, incl, off);
            if (lane >= off) incl += t;
        }
        if (lane == 31) wsum[wid] = incl;
        __syncthreads();
        if (wid == 0) {
            int w = wsum[lane];
            int wi = w;
#pragma unroll
            for (int off = 1; off < 32; off <<= 1) {
                int t = __shfl_up_sync(0xFFFFFFFFu, wi, off);
                if (lane >= off) wi += t;
            }
            wsum[lane] = wi - w;     // exclusive warp offsets
        }
        __syncthreads();
        int c = s_carry;
        int excl = c + wsum[wid] + incl - v;
        if (i < NN) {
            g_row[i] = excl;
            g_cur[i] = excl;
        }
        __syncthreads();
        if (tid == 1023) s_carry = c + wsum[31] + incl;   // last thread has block total
        __syncthreads();
    }
    if (tid == 0) g_row[NN] = s_carry;
}

__global__ void place_k() {
    int e = blockIdx.x * blockDim.x + threadIdx.x;
    if (e >= NE) return;
    int p = atomicAdd(&g_cur[g_dst[e]], 1);
    g_csr_src[p] = g_src[e];
}

// ---------------- SGEMM: C[M,N] = A[M,K] @ B[K,N] ----------------
__global__ __launch_bounds__(256) void sgemm_k(const float* __restrict__ A,
                                               const float* __restrict__ B,
                                               float* __restrict__ C,
                                               int M, int N, int K) {
    __shared__ __align__(16) float As[16][128];
    __shared__ __align__(16) float Bs[16][64];
    const int tid = threadIdx.x;
    const int tx = tid & 15, ty = tid >> 4;
    const int m0 = blockIdx.y * 128, n0 = blockIdx.x * 64;

    float acc[8][4];
#pragma unroll
    for (int i = 0; i < 8; i++)
#pragma unroll
        for (int j = 0; j < 4; j++) acc[i][j] = 0.f;

    for (int k0 = 0; k0 < K; k0 += 16) {
#pragma unroll
        for (int v = 0; v < 2; v++) {
            int id  = tid + v * 256;
            int row = id >> 2;
            int kc  = (id & 3) << 2;
            float4 f = make_float4(0.f, 0.f, 0.f, 0.f);
            int gr = m0 + row;
            if (gr < M) f = *(const float4*)(A + (size_t)gr * K + k0 + kc);
            As[kc + 0][row] = f.x; As[kc + 1][row] = f.y;
            As[kc + 2][row] = f.z; As[kc + 3][row] = f.w;
        }
        {
            int kk = tid >> 4;
            int nc = (tid & 15) << 2;
            *(float4*)&Bs[kk][nc] = *(const float4*)(B + (size_t)(k0 + kk) * N + n0 + nc);
        }
        __syncthreads();
#pragma unroll
        for (int kk = 0; kk < 16; kk++) {
            float a[8], b[4];
            *(float4*)&a[0] = *(const float4*)&As[kk][ty * 8];
            *(float4*)&a[4] = *(const float4*)&As[kk][ty * 8 + 4];
            *(float4*)&b[0] = *(const float4*)&Bs[kk][tx * 4];
#pragma unroll
            for (int i = 0; i < 8; i++)
#pragma unroll
                for (int j = 0; j < 4; j++) acc[i][j] = fmaf(a[i], b[j], acc[i][j]);
        }
        __syncthreads();
    }
#pragma unroll
    for (int i = 0; i < 8; i++) {
        int gr = m0 + ty * 8 + i;
        if (gr < M)
            *(float4*)(C + (size_t)gr * N + n0 + tx * 4) =
                make_float4(acc[i][0], acc[i][1], acc[i][2], acc[i][3]);
    }
}

// ---------------- attention coefficients ----------------
__global__ void al1_k(const float* __restrict__ a_src, const float* __restrict__ a_dst) {
    int t = blockIdx.x * blockDim.x + threadIdx.x;
    if (t >= NN * HEADS) return;
    int n = t >> 2, h = t & 3;
    const float4* hr = (const float4*)(g_h1 + (size_t)n * D1 + h * HID);
    const float4* as = (const float4*)(a_src + h * HID);
    const float4* ad = (const float4*)(a_dst + h * HID);
    float ss = 0.f, sd = 0.f;
#pragma unroll
    for (int j = 0; j < 16; j++) {
        float4 v = hr[j], a = as[j], b = ad[j];
        ss += v.x * a.x + v.y * a.y + v.z * a.z + v.w * a.w;
        sd += v.x * b.x + v.y * b.y + v.z * b.z + v.w * b.w;
    }
    g_als1[t] = ss;
    g_ald1[t] = sd;
}

__global__ void al2_k(const float* __restrict__ a_src, const float* __restrict__ a_dst) {
    int n = blockIdx.x * blockDim.x + threadIdx.x;
    if (n >= NN) return;
    const float4* hr = (const float4*)(g_h2 + (size_t)n * HID);
    const float4* as = (const float4*)a_src;
    const float4* ad = (const float4*)a_dst;
    float ss = 0.f, sd = 0.f;
#pragma unroll
    for (int j = 0; j < 16; j++) {
        float4 v = hr[j], a = as[j], b = ad[j];
        ss += v.x * a.x + v.y * a.y + v.z * a.z + v.w * a.w;
        sd += v.x * b.x + v.y * b.y + v.z * b.z + v.w * b.w;
    }
    g_als2[n] = ss;
    g_ald2[n] = sd;
}

// ---------------- layer 1: fused softmax + aggregate + bias + relu ----------
// warp per dst node; lane owns channels [lane*8, lane*8+8), head h = lane>>3
__global__ __launch_bounds__(256) void agg1_k(const float* __restrict__ b1) {
    int node = (blockIdx.x * blockDim.x + threadIdx.x) >> 5;
    int lane = threadIdx.x & 31;
    if (node >= NN) return;
    const int h = lane >> 3;
    const int beg = g_row[node], end = g_row[node + 1];

    const float ald = g_ald1[node * 4 + h];
    const float selfev = leaky(g_als1[node * 4 + h] + ald);

    // pass 1: per-head max over incident edges (+ self)
    float m = selfev;
    for (int i = beg; i < end; i++) {
        int s = g_csr_src[i];
        m = fmaxf(m, leaky(g_als1[s * 4 + h] + ald));
    }

    // pass 2: accumulate exp-weighted messages and denominator
    float ex = __expf(selfev - m);
    float den = ex;
    float acc[8];
    {
        const float4* hp = (const float4*)(g_h1 + (size_t)node * D1 + lane * 8);
        float4 v0 = hp[0], v1 = hp[1];
        acc[0] = ex * v0.x; acc[1] = ex * v0.y; acc[2] = ex * v0.z; acc[3] = ex * v0.w;
        acc[4] = ex * v1.x; acc[5] = ex * v1.y; acc[6] = ex * v1.z; acc[7] = ex * v1.w;
    }
    for (int i = beg; i < end; i++) {
        int s = g_csr_src[i];
        float ev = leaky(g_als1[s * 4 + h] + ald);
        float w = __expf(ev - m);
        den += w;
        const float4* hp = (const float4*)(g_h1 + (size_t)s * D1 + lane * 8);
        float4 v0 = hp[0], v1 = hp[1];
        acc[0] = fmaf(w, v0.x, acc[0]); acc[1] = fmaf(w, v0.y, acc[1]);
        acc[2] = fmaf(w, v0.z, acc[2]); acc[3] = fmaf(w, v0.w, acc[3]);
        acc[4] = fmaf(w, v1.x, acc[4]); acc[5] = fmaf(w, v1.y, acc[5]);
        acc[6] = fmaf(w, v1.z, acc[6]); acc[7] = fmaf(w, v1.w, acc[7]);
    }
    float inv = 1.f / (den + 1e-16f);
    const float4* bp = (const float4*)(b1 + lane * 8);
    float4 b0 = bp[0], b4 = bp[1];
    float4 o0 = make_float4(fmaxf(fmaf(acc[0], inv, b0.x), 0.f),
                            fmaxf(fmaf(acc[1], inv, b0.y), 0.f),
                            fmaxf(fmaf(acc[2], inv, b0.z), 0.f),
                            fmaxf(fmaf(acc[3], inv, b0.w), 0.f));
    float4 o1 = make_float4(fmaxf(fmaf(acc[4], inv, b4.x), 0.f),
                            fmaxf(fmaf(acc[5], inv, b4.y), 0.f),
                            fmaxf(fmaf(acc[6], inv, b4.z), 0.f),
                            fmaxf(fmaf(acc[7], inv, b4.w), 0.f));
    float4* op = (float4*)(g_out1 + (size_t)node * D1 + lane * 8);
    op[0] = o0; op[1] = o1;
}

// ---------------- layer 2: fused softmax + aggregate + bias + pool ----------
// warp per dst node; lane owns channels [lane*2, lane*2+2); H=1
__global__ __launch_bounds__(256) void agg2_k(const float* __restrict__ b2) {
    int node = (blockIdx.x * blockDim.x + threadIdx.x) >> 5;
    int lane = threadIdx.x & 31;
    if (node >= NN) return;
    const int beg = g_row[node], end = g_row[node + 1];

    const float ald = g_ald2[node];
    const float selfev = leaky(g_als2[node] + ald);

    float m = selfev;
    for (int i = beg; i < end; i++) {
        int s = g_csr_src[i];
        m = fmaxf(m, leaky(g_als2[s] + ald));
    }

    float ex = __expf(selfev - m);
    float den = ex;
    float a0, a1;
    {
        float2 v = *(const float2*)(g_h2 + (size_t)node * HID + lane * 2);
        a0 = ex * v.x; a1 = ex * v.y;
    }
    for (int i = beg; i < end; i++) {
        int s = g_csr_src[i];
        float w = __expf(leaky(g_als2[s] + ald) - m);
        den += w;
        float2 v = *(const float2*)(g_h2 + (size_t)s * HID + lane * 2);
        a0 = fmaf(w, v.x, a0);
        a1 = fmaf(w, v.y, a1);
    }
    float inv = 1.f / (den + 1e-16f);
    float2 bb = *(const float2*)(b2 + lane * 2);
    float v0 = fmaf(a0, inv, bb.x);
    float v1 = fmaf(a1, inv, bb.y);

    // pack even/odd lane pairs into one red4 (16B-aligned)
    float u0 = __shfl_down_sync(0xFFFFFFFFu, v0, 1);
    float u1 = __shfl_down_sync(0xFFFFFFFFu, v1, 1);
    if ((lane & 1) == 0) {
        int g = g_bat[node];
        red4(&g_pool[g * HID + lane * 2], make_float4(v0, v1, u0, u1));
    }
}

// ---------------- pooling + classifier ----------------
__global__ void zeropool_k() {
    int t = blockIdx.x * blockDim.x + threadIdx.x;
    if (t < NG * HID) g_pool[t] = 0.f;
}

__global__ void cls_k(const float* __restrict__ fcw, const float* __restrict__ fcb,
                      float* __restrict__ out) {
    int g = blockIdx.x * blockDim.x + threadIdx.x;
    if (g >= NG) return;
    float l[OUTC];
#pragma unroll
    for (int j = 0; j < OUTC; j++) l[j] = fcb[j];
    for (int k = 0; k < HID; k++) {
        float p = g_pool[g * HID + k];
#pragma unroll
        for (int j = 0; j < OUTC; j++) l[j] = fmaf(p, fcw[k * OUTC + j], l[j]);
    }
    float mx = l[0];
#pragma unroll
    for (int j = 1; j < OUTC; j++) mx = fmaxf(mx, l[j]);
    float s = 0.f;
#pragma unroll
    for (int j = 0; j < OUTC; j++) s += expf(l[j] - mx);
    float lse = mx + logf(s);
#pragma unroll
    for (int j = 0; j < OUTC; j++) out[g * OUTC + j] = l[j] - lse;
}

// ---------------- launch ----------------
extern "C" void kernel_launch(void* const* d_in, const int* in_sizes, int n_in,
                              void* d_out, int out_size) {
    const float* x      = (const float*)d_in[0];
    const int*   ei_raw = (const int*)d_in[1];
    const int*   b_raw  = (const int*)d_in[2];
    const float* W1     = (const float*)d_in[3];
    const float* a_src1 = (const float*)d_in[4];
    const float* a_dst1 = (const float*)d_in[5];
    const float* b1     = (const float*)d_in[6];
    const float* W2     = (const float*)d_in[7];
    const float* a_src2 = (const float*)d_in[8];
    const float* a_dst2 = (const float*)d_in[9];
    const float* b2     = (const float*)d_in[10];
    const float* fcw    = (const float*)d_in[11];
    const float* fcb    = (const float*)d_in[12];
    float*       out    = (float*)d_out;

    void *p_h1, *p_out1, *p_h2;
    cudaGetSymbolAddress(&p_h1, g_h1);
    cudaGetSymbolAddress(&p_out1, g_out1);
    cudaGetSymbolAddress(&p_h2, g_h2);

    const int T = 256;
    const int gN4 = (NN * HEADS + T - 1) / T;
    const int gN  = (NN + T - 1) / T;
    const int gE  = (NE + T - 1) / T;
    const int gNw = (NN * 32 + T - 1) / T;   // warp per node

    // ---- index conversion + CSR build ----
    detect_k<<<1, 32>>>(ei_raw);
    zero_deg_k<<<gN, T>>>();
    cvt_edges_k<<<gE, T>>>(ei_raw);
    cvt_batch_k<<<gN, T>>>(b_raw);
    scan_k<<<1, 1024>>>();
    place_k<<<gE, T>>>();

    // ---- GAT layer 1 ----
    sgemm_k<<<dim3(D1 / 64, (NN + 127) / 128), 256>>>(x, W1, (float*)p_h1, NN, D1, INC);
    al1_k<<<gN4, T>>>(a_src1, a_dst1);
    agg1_k<<<gNw, T>>>(b1);

    // ---- GAT layer 2 (+ fused pooling) ----
    sgemm_k<<<dim3(HID / 64, (NN + 127) / 128), 256>>>((const float*)p_out1, W2,
                                                       (float*)p_h2, NN, HID, D1);
    al2_k<<<gN, T>>>(a_src2, a_dst2);
    zeropool_k<<<(NG * HID + T - 1) / T, T>>>();
    agg2_k<<<gNw, T>>>(b2);

    // ---- classifier ----
    cls_k<<<(NG + T - 1) / T, T>>>(fcw, fcb, out);
}